// round 12
// baseline (speedup 1.0000x reference)
#include <cuda_runtime.h>
#include <cuda_fp16.h>
#include <cstdint>
#include <cstddef>

// Problem dims
#define DI    4096
#define MROWS 8192          // 4*2048
#define NOUT  4096
#define WN    (4096*4096)

// GEMM tiling (legacy mma.sync path — tcgen05 unavailable at compute_103)
#define BM 128
#define BN 256
#define BK 64               // 64 fp16 = 128B rows -> conflict-free xor swizzle
#define NSTG 4
#define NCHUNK (DI/BK)      // 64
#define A_BYTES (BM*BK*2)   // 16384
#define B_BYTES (BN*BK*2)   // 32768
#define STAGE_BYTES (A_BYTES + B_BYTES)          // 49152
#define SMEM_TOTAL (NSTG*STAGE_BYTES)            // 196608
#define NTHR 512

#define WSUM_BLOCKS 512
#define BIN_BLOCKS  2048

// Scratch (no cudaMalloc allowed)
__device__ __half g_xn[(size_t)MROWS * DI];   // 64 MB fp16 layernormed x
__device__ __half g_wb[(size_t)WN];           // 32 MB fp16 binarized weight
__device__ float  g_part1[WSUM_BLOCKS];
__device__ float  g_part2[BIN_BLOCKS];
__device__ float  g_wmean;
__device__ float  g_beta;
__device__ unsigned g_ctr1 = 0;
__device__ unsigned g_ctr2 = 0;

// ---------------- reduction helpers ----------------
__device__ __forceinline__ float warp_sum(float v) {
#pragma unroll
    for (int o = 16; o > 0; o >>= 1) v += __shfl_xor_sync(0xFFFFFFFFu, v, o);
    return v;
}

__device__ __forceinline__ float block_sum256(float v) {
    __shared__ float sh[8];
    float s = warp_sum(v);
    if ((threadIdx.x & 31) == 0) sh[threadIdx.x >> 5] = s;
    __syncthreads();
    float t = 0.f;
    if (threadIdx.x == 0) {
#pragma unroll
        for (int i = 0; i < 8; i++) t += sh[i];
    }
    return t;   // valid on thread 0 only
}

__device__ __forceinline__ float4 ldcs4(const float4* p) {
    float4 v;
    asm volatile("ld.global.cs.v4.f32 {%0,%1,%2,%3}, [%4];"
                 : "=f"(v.x), "=f"(v.y), "=f"(v.z), "=f"(v.w) : "l"(p));
    return v;
}
__device__ __forceinline__ void stcs2h(__half2* p, __half2 a, __half2 b) {
    uint32_t ua = *(uint32_t*)&a, ub = *(uint32_t*)&b;
    asm volatile("st.global.cs.v2.b32 [%0], {%1,%2};" :: "l"(p), "r"(ua), "r"(ub) : "memory");
}
__device__ __forceinline__ void stcs4h(void* p, __half2 a, __half2 b, __half2 c, __half2 d) {
    uint32_t ua = *(uint32_t*)&a, ub = *(uint32_t*)&b, uc = *(uint32_t*)&c, ud = *(uint32_t*)&d;
    asm volatile("st.global.cs.v4.b32 [%0], {%1,%2,%3,%4};"
                 :: "l"(p), "r"(ua), "r"(ub), "r"(uc), "r"(ud) : "memory");
}

// ---------------- k1: LayerNorm rows + W-sum partials + mean (fused) ----------------
__global__ void k_ln_wsum(const float* __restrict__ x, const float* __restrict__ w) {
    if (blockIdx.x < MROWS) {
        // ---- LayerNorm one row ----
        const int row = blockIdx.x;
        const float4* xr = (const float4*)(x + (size_t)row * DI);
        float4 v[4];
        float s = 0.f, ss = 0.f;
#pragma unroll
        for (int i = 0; i < 4; i++) {
            v[i] = ldcs4(xr + threadIdx.x + i * 256);   // streaming: x never re-read
            s  += v[i].x + v[i].y + v[i].z + v[i].w;
            ss += v[i].x * v[i].x + v[i].y * v[i].y + v[i].z * v[i].z + v[i].w * v[i].w;
        }
        __shared__ float shS[8], shQ[8], bc[2];
        float rs = warp_sum(s), rq = warp_sum(ss);
        if ((threadIdx.x & 31) == 0) { shS[threadIdx.x >> 5] = rs; shQ[threadIdx.x >> 5] = rq; }
        __syncthreads();
        if (threadIdx.x == 0) {
            float ts = 0.f, tq = 0.f;
#pragma unroll
            for (int i = 0; i < 8; i++) { ts += shS[i]; tq += shQ[i]; }
            float mu  = ts * (1.f / (float)DI);
            float var = tq * (1.f / (float)DI) - mu * mu;
            bc[0] = mu;
            bc[1] = rsqrtf(var + 1e-5f);
        }
        __syncthreads();
        const float mu = bc[0], rstd = bc[1];
        __half2* o = (__half2*)(g_xn + (size_t)row * DI);
#pragma unroll
        for (int i = 0; i < 4; i++) {
            int idx = threadIdx.x + i * 256;
            float4 t = v[i];
            // 8B store at byte offset 8*idx — correctly aligned (v4 here was the R10 bug)
            stcs2h(o + 2 * idx,
                   __floats2half2_rn((t.x - mu) * rstd, (t.y - mu) * rstd),
                   __floats2half2_rn((t.z - mu) * rstd, (t.w - mu) * rstd));
        }
    } else {
        // ---- W-sum partials (default caching: keep W in L2 for k2) ----
        const int b = blockIdx.x - MROWS;
        float s = 0.f;
        const float4* w4 = (const float4*)w;
        for (int i = b * 256 + threadIdx.x; i < WN / 4; i += WSUM_BLOCKS * 256) {
            float4 v = w4[i];
            s += v.x + v.y + v.z + v.w;
        }
        float t = block_sum256(s);
        if (threadIdx.x == 0) g_part1[b] = t;
    }

    // ---- last-block final reduction of mean (deterministic fixed-order) ----
    __shared__ unsigned done;
    __threadfence();
    __syncthreads();
    if (threadIdx.x == 0) done = atomicAdd(&g_ctr1, 1u);
    __syncthreads();
    if (done == (unsigned)(MROWS + WSUM_BLOCKS - 1)) {
        float s = 0.f;
        for (int i = threadIdx.x; i < WSUM_BLOCKS; i += 256) s += g_part1[i];
        float t = block_sum256(s);
        if (threadIdx.x == 0) {
            g_wmean = t / (float)WN;
            g_ctr1 = 0;         // reset for next graph replay
            __threadfence();
        }
    }
}

// ---------------- k2: binarize W + |.| partials + beta (fused) ----------------
__global__ void k_binabs_beta(const float* __restrict__ w) {
    const float m = g_wmean;
    float s = 0.f;
    const float4* w4 = (const float4*)w;
    __half2* o = (__half2*)g_wb;
    for (int j = blockIdx.x * 256 + threadIdx.x; j < WN / 8; j += BIN_BLOCKS * 256) {
        float4 v0 = w4[2 * j];
        float4 v1 = w4[2 * j + 1];
        float a = v0.x - m, b = v0.y - m, c = v0.z - m, d = v0.w - m;
        float e = v1.x - m, f = v1.y - m, g2 = v1.z - m, h = v1.w - m;
        s += fabsf(a) + fabsf(b) + fabsf(c) + fabsf(d)
           + fabsf(e) + fabsf(f) + fabsf(g2) + fabsf(h);
        float sa = (a > 0.f) ? 1.f : ((a < 0.f) ? -1.f : 0.f);
        float sb = (b > 0.f) ? 1.f : ((b < 0.f) ? -1.f : 0.f);
        float sc = (c > 0.f) ? 1.f : ((c < 0.f) ? -1.f : 0.f);
        float sd = (d > 0.f) ? 1.f : ((d < 0.f) ? -1.f : 0.f);
        float se = (e > 0.f) ? 1.f : ((e < 0.f) ? -1.f : 0.f);
        float sf = (f > 0.f) ? 1.f : ((f < 0.f) ? -1.f : 0.f);
        float sg = (g2 > 0.f) ? 1.f : ((g2 < 0.f) ? -1.f : 0.f);
        float sh2 = (h > 0.f) ? 1.f : ((h < 0.f) ? -1.f : 0.f);
        // 16B store at byte offset 16*j — aligned, covers exactly elements 8j..8j+7
        stcs4h(o + 4 * j,
               __floats2half2_rn(sa, sb), __floats2half2_rn(sc, sd),
               __floats2half2_rn(se, sf), __floats2half2_rn(sg, sh2));
    }
    float t = block_sum256(s);
    if (threadIdx.x == 0) g_part2[blockIdx.x] = t;

    __shared__ unsigned done;
    __threadfence();
    __syncthreads();
    if (threadIdx.x == 0) done = atomicAdd(&g_ctr2, 1u);
    __syncthreads();
    if (done == (unsigned)(BIN_BLOCKS - 1)) {
        float s2 = 0.f;
        for (int i = threadIdx.x; i < BIN_BLOCKS; i += 256) s2 += g_part2[i];
        float t2 = block_sum256(s2);
        if (threadIdx.x == 0) {
            g_beta = t2 / (float)WN;
            g_ctr2 = 0;
            __threadfence();
        }
    }
}

// ---------------- PTX helpers (baseline sm_80-class only) ----------------
__device__ __forceinline__ uint32_t smem_u32(const void* p) {
    uint32_t a;
    asm("{ .reg .u64 t; cvta.to.shared.u64 t, %1; cvt.u32.u64 %0, t; }" : "=r"(a) : "l"(p));
    return a;
}
__device__ __forceinline__ void cpa16(uint32_t d, const void* g) {
    asm volatile("cp.async.cg.shared.global [%0], [%1], 16;" :: "r"(d), "l"(g) : "memory");
}
#define CP_COMMIT() asm volatile("cp.async.commit_group;" ::: "memory")
#define CP_WAIT1()  asm volatile("cp.async.wait_group 1;" ::: "memory")

__device__ __forceinline__ void ldsm4(uint32_t* r, uint32_t a) {
    asm volatile("ldmatrix.sync.aligned.m8n8.x4.shared.b16 {%0,%1,%2,%3}, [%4];"
                 : "=r"(r[0]), "=r"(r[1]), "=r"(r[2]), "=r"(r[3]) : "r"(a));
}
__device__ __forceinline__ void mma16816(float* c, const uint32_t* a, const uint32_t* b) {
    asm volatile("mma.sync.aligned.m16n8k16.row.col.f32.f16.f16.f32 "
                 "{%0,%1,%2,%3}, {%4,%5,%6,%7}, {%8,%9}, {%0,%1,%2,%3};"
                 : "+f"(c[0]), "+f"(c[1]), "+f"(c[2]), "+f"(c[3])
                 : "r"(a[0]), "r"(a[1]), "r"(a[2]), "r"(a[3]), "r"(b[0]), "r"(b[1]));
}

// ---------------- GEMM ----------------
__device__ __forceinline__ void load_stage(uint32_t sb, int s,
                                           const __half* Abase, const __half* Bbase,
                                           int chunk, int tid) {
    const uint32_t stA = sb + (uint32_t)s * STAGE_BYTES;
    const uint32_t stB = stA + A_BYTES;
    const size_t kb = (size_t)chunk * BK;
#pragma unroll
    for (int it = 0; it < 6; it++) {
        int i = tid + it * NTHR;
        if (i < BM * 8) {                 // A: 128 rows x 8 segments(16B)
            int r = i >> 3, cs = i & 7;
            const void* g = Abase + (size_t)r * DI + kb + cs * 8;
            uint32_t off = (uint32_t)(r * 128 + cs * 16);
            cpa16(stA + (off ^ ((uint32_t)(r & 7) << 4)), g);
        } else {                          // B: 256 rows x 8 segments
            int j = i - BM * 8;
            int r = j >> 3, cs = j & 7;
            const void* g = Bbase + (size_t)r * DI + kb + cs * 8;
            uint32_t off = (uint32_t)(r * 128 + cs * 16);
            cpa16(stB + (off ^ ((uint32_t)(r & 7) << 4)), g);
        }
    }
    CP_COMMIT();
}

__global__ void __launch_bounds__(NTHR, 1) k_gemm(float* __restrict__ out) {
    extern __shared__ char smem[];
    const uint32_t sb = smem_u32(smem);
    const int tid = threadIdx.x;
    const int wid = tid >> 5, lane = tid & 31;
    const int wm = wid >> 2, wn = wid & 3;           // warp grid 4(M) x 4(N), warp tile 32x64
    const int lr = lane & 7, sel = lane >> 3;
    const int g = lane >> 2, tc = lane & 3;

    // CTA swizzle: groups of 8 m-tiles x 16 n-tiles (128 CTAs ~ 1 wave) for L2 reuse
    const int grp = blockIdx.x >> 7;
    const int rem = blockIdx.x & 127;
    const int mt = grp * 8 + (rem & 7);              // 0..63
    const int nt = rem >> 3;                         // 0..15

    const __half* Abase = g_xn + (size_t)mt * BM * DI;
    const __half* Bbase = g_wb + (size_t)nt * BN * DI;

    float acc[2][8][4];
#pragma unroll
    for (int i = 0; i < 2; i++)
#pragma unroll
        for (int j = 0; j < 8; j++)
#pragma unroll
            for (int k = 0; k < 4; k++) acc[i][j][k] = 0.f;

    // A frag (m16k16 per ldsm4): rows wm*32 + lr + (sel&1)*8 + i*16, k-half (sel>>1)*16B
    const int a_row = wm * 32 + lr + (sel & 1) * 8;
    const uint32_t a_k2 = (uint32_t)((sel >> 1) * 16);      // bytes
    // B frag (k16n16 per ldsm4, [n][k] smem): n rows wn*64 + lr + (sel>>1)*8 + p*16, k-half (sel&1)*16B
    const int b_row = wn * 64 + lr + (sel >> 1) * 8;
    const uint32_t b_k2 = (uint32_t)((sel & 1) * 16);       // bytes
    const uint32_t xr = (uint32_t)lr << 4;

    // Double-buffered register fragments
    uint32_t af[2][2][4];
    uint32_t bf[2][4][4];

    // prologue: fill 3 of 4 stages
    load_stage(sb, 0, Abase, Bbase, 0, tid);
    load_stage(sb, 1, Abase, Bbase, 1, tid);
    load_stage(sb, 2, Abase, Bbase, 2, tid);
    CP_WAIT1();                     // chunks 0,1 complete
    __syncthreads();

    // preload kstep0 fragments of chunk 0 into buffer 0
    {
        const uint32_t sA = sb;
        const uint32_t sB = sA + A_BYTES;
#pragma unroll
        for (int i = 0; i < 2; i++)
            ldsm4(af[0][i], sA + (uint32_t)(a_row + i * 16) * 128 + (a_k2 ^ xr));
#pragma unroll
        for (int p = 0; p < 4; p++)
            ldsm4(bf[0][p], sB + (uint32_t)(b_row + p * 16) * 128 + (b_k2 ^ xr));
    }

    int s = 0;
    for (int ks = 0; ks < NCHUNK; ks++) {
        CP_WAIT1();                 // chunks 0..ks+1 complete
        __syncthreads();            // stage reuse + cross-warp visibility of chunks ks, ks+1

        {   // issue next-stage loads (always commit a group to keep wait bookkeeping exact)
            const int nxt = ks + 3;
            if (nxt < NCHUNK) {
                int sn = s + 3; if (sn >= NSTG) sn -= NSTG;
                load_stage(sb, sn, Abase, Bbase, nxt, tid);
            } else {
                CP_COMMIT();
            }
        }

        const uint32_t sA = sb + (uint32_t)s * STAGE_BYTES;
        const uint32_t sB = sA + A_BYTES;
        // next chunk's stage (for cross-chunk kstep0 prefetch; clamp at last chunk)
        int s2 = (ks + 1 < NCHUNK) ? (s + 1 == NSTG ? 0 : s + 1) : s;
        const uint32_t sA2 = sb + (uint32_t)s2 * STAGE_BYTES;
        const uint32_t sB2 = sA2 + A_BYTES;

#pragma unroll
        for (int kk = 0; kk < 4; kk++) {             // 4 ksteps of 16 within BK=64
            const int cb = kk & 1, nb = cb ^ 1;
            // prefetch fragments for next kstep (or next chunk's kstep0) into other buffer
            const uint32_t nA = (kk < 3) ? sA : sA2;
            const uint32_t nB = (kk < 3) ? sB : sB2;
            const uint32_t ncol = (kk < 3) ? (uint32_t)((kk + 1) * 32) : 0u;
#pragma unroll
            for (int i = 0; i < 2; i++)
                ldsm4(af[nb][i], nA + (uint32_t)(a_row + i * 16) * 128 + ((ncol + a_k2) ^ xr));
#pragma unroll
            for (int p = 0; p < 4; p++)
                ldsm4(bf[nb][p], nB + (uint32_t)(b_row + p * 16) * 128 + ((ncol + b_k2) ^ xr));
            // compute current kstep
#pragma unroll
            for (int i = 0; i < 2; i++)
#pragma unroll
                for (int j = 0; j < 8; j++)
                    mma16816(acc[i][j], af[cb][i], &bf[cb][j >> 1][(j & 1) * 2]);
        }

        s++; if (s == NSTG) s = 0;
    }

    // epilogue (streaming stores: out is write-once)
    const float beta = g_beta;
    const int rbase = mt * BM + wm * 32 + g;
    const int cbase = nt * BN + wn * 64 + tc * 2;
#pragma unroll
    for (int i = 0; i < 2; i++) {
#pragma unroll
        for (int j = 0; j < 8; j += 2) {
            const int row = rbase + i * 16;
            const int col = cbase + j * 8;
            float2 v0 = make_float2(acc[i][j][0] * beta, acc[i][j][1] * beta);
            float2 v1 = make_float2(acc[i][j][2] * beta, acc[i][j][3] * beta);
            float2 w0 = make_float2(acc[i][j + 1][0] * beta, acc[i][j + 1][1] * beta);
            float2 w1 = make_float2(acc[i][j + 1][2] * beta, acc[i][j + 1][3] * beta);
            asm volatile("st.global.cs.v2.f32 [%0], {%1,%2};" :: "l"(out + (size_t)row * NOUT + col), "f"(v0.x), "f"(v0.y) : "memory");
            asm volatile("st.global.cs.v2.f32 [%0], {%1,%2};" :: "l"(out + (size_t)(row + 8) * NOUT + col), "f"(v1.x), "f"(v1.y) : "memory");
            asm volatile("st.global.cs.v2.f32 [%0], {%1,%2};" :: "l"(out + (size_t)row * NOUT + col + 8), "f"(w0.x), "f"(w0.y) : "memory");
            asm volatile("st.global.cs.v2.f32 [%0], {%1,%2};" :: "l"(out + (size_t)(row + 8) * NOUT + col + 8), "f"(w1.x), "f"(w1.y) : "memory");
        }
    }
}

// ---------------- launch ----------------
extern "C" void kernel_launch(void* const* d_in, const int* in_sizes, int n_in,
                              void* d_out, int out_size) {
    (void)in_sizes; (void)n_in; (void)out_size;
    const float* x = (const float*)d_in[0];
    const float* w = (const float*)d_in[1];
    float* out = (float*)d_out;

    cudaFuncSetAttribute(k_gemm, cudaFuncAttributeMaxDynamicSharedMemorySize, SMEM_TOTAL);

    k_ln_wsum<<<MROWS + WSUM_BLOCKS, 256>>>(x, w);
    k_binabs_beta<<<BIN_BLOCKS, 256>>>(w);
    k_gemm<<<(MROWS / BM) * (NOUT / BN), NTHR, SMEM_TOTAL>>>(out);
}

// round 13
// speedup vs baseline: 1.0340x; 1.0340x over previous
#include <cuda_runtime.h>
#include <cuda_fp16.h>
#include <cstdint>
#include <cstddef>

// Problem dims
#define DI    4096
#define MROWS 8192          // 4*2048
#define NOUT  4096
#define WN    (4096*4096)

// GEMM tiling (legacy mma.sync path — tcgen05 unavailable at compute_103)
#define BM 128
#define BN 256
#define BK 64               // 64 fp16 = 128B rows -> conflict-free xor swizzle
#define NSTG 4
#define NCHUNK (DI/BK)      // 64
#define A_BYTES (BM*BK*2)   // 16384
#define B_BYTES (BN*BK*2)   // 32768
#define STAGE_BYTES (A_BYTES + B_BYTES)          // 49152
#define SMEM_TOTAL (NSTG*STAGE_BYTES)            // 196608
#define NTHR 256            // 8 warps, 64x64 warp tiles -> halves smem read traffic

#define WSUM_BLOCKS 512
#define BIN_BLOCKS  2048

// Scratch (no cudaMalloc allowed)
__device__ __half g_xn[(size_t)MROWS * DI];   // 64 MB fp16 layernormed x
__device__ __half g_wb[(size_t)WN];           // 32 MB fp16 binarized weight
__device__ float  g_part1[WSUM_BLOCKS];
__device__ float  g_part2[BIN_BLOCKS];
__device__ float  g_wmean;
__device__ float  g_beta;
__device__ unsigned g_ctr1 = 0;
__device__ unsigned g_ctr2 = 0;

// ---------------- reduction helpers ----------------
__device__ __forceinline__ float warp_sum(float v) {
#pragma unroll
    for (int o = 16; o > 0; o >>= 1) v += __shfl_xor_sync(0xFFFFFFFFu, v, o);
    return v;
}

__device__ __forceinline__ float block_sum256(float v) {
    __shared__ float sh[8];
    float s = warp_sum(v);
    if ((threadIdx.x & 31) == 0) sh[threadIdx.x >> 5] = s;
    __syncthreads();
    float t = 0.f;
    if (threadIdx.x == 0) {
#pragma unroll
        for (int i = 0; i < 8; i++) t += sh[i];
    }
    return t;   // valid on thread 0 only
}

__device__ __forceinline__ float4 ldcs4(const float4* p) {
    float4 v;
    asm volatile("ld.global.cs.v4.f32 {%0,%1,%2,%3}, [%4];"
                 : "=f"(v.x), "=f"(v.y), "=f"(v.z), "=f"(v.w) : "l"(p));
    return v;
}
__device__ __forceinline__ void stcs2h(__half2* p, __half2 a, __half2 b) {
    uint32_t ua = *(uint32_t*)&a, ub = *(uint32_t*)&b;
    asm volatile("st.global.cs.v2.b32 [%0], {%1,%2};" :: "l"(p), "r"(ua), "r"(ub) : "memory");
}
__device__ __forceinline__ void stcs4h(void* p, __half2 a, __half2 b, __half2 c, __half2 d) {
    uint32_t ua = *(uint32_t*)&a, ub = *(uint32_t*)&b, uc = *(uint32_t*)&c, ud = *(uint32_t*)&d;
    asm volatile("st.global.cs.v4.b32 [%0], {%1,%2,%3,%4};"
                 :: "l"(p), "r"(ua), "r"(ub), "r"(uc), "r"(ud) : "memory");
}

// ---------------- k1: LayerNorm rows + W-sum partials + mean (fused) ----------------
__global__ void k_ln_wsum(const float* __restrict__ x, const float* __restrict__ w) {
    if (blockIdx.x < MROWS) {
        // ---- LayerNorm one row ----
        const int row = blockIdx.x;
        const float4* xr = (const float4*)(x + (size_t)row * DI);
        float4 v[4];
        float s = 0.f, ss = 0.f;
#pragma unroll
        for (int i = 0; i < 4; i++) {
            v[i] = ldcs4(xr + threadIdx.x + i * 256);   // streaming: x never re-read
            s  += v[i].x + v[i].y + v[i].z + v[i].w;
            ss += v[i].x * v[i].x + v[i].y * v[i].y + v[i].z * v[i].z + v[i].w * v[i].w;
        }
        __shared__ float shS[8], shQ[8], bc[2];
        float rs = warp_sum(s), rq = warp_sum(ss);
        if ((threadIdx.x & 31) == 0) { shS[threadIdx.x >> 5] = rs; shQ[threadIdx.x >> 5] = rq; }
        __syncthreads();
        if (threadIdx.x == 0) {
            float ts = 0.f, tq = 0.f;
#pragma unroll
            for (int i = 0; i < 8; i++) { ts += shS[i]; tq += shQ[i]; }
            float mu  = ts * (1.f / (float)DI);
            float var = tq * (1.f / (float)DI) - mu * mu;
            bc[0] = mu;
            bc[1] = rsqrtf(var + 1e-5f);
        }
        __syncthreads();
        const float mu = bc[0], rstd = bc[1];
        __half2* o = (__half2*)(g_xn + (size_t)row * DI);
#pragma unroll
        for (int i = 0; i < 4; i++) {
            int idx = threadIdx.x + i * 256;
            float4 t = v[i];
            stcs2h(o + 2 * idx,
                   __floats2half2_rn((t.x - mu) * rstd, (t.y - mu) * rstd),
                   __floats2half2_rn((t.z - mu) * rstd, (t.w - mu) * rstd));
        }
    } else {
        // ---- W-sum partials (default caching: keep W in L2 for k2) ----
        const int b = blockIdx.x - MROWS;
        float s = 0.f;
        const float4* w4 = (const float4*)w;
        for (int i = b * 256 + threadIdx.x; i < WN / 4; i += WSUM_BLOCKS * 256) {
            float4 v = w4[i];
            s += v.x + v.y + v.z + v.w;
        }
        float t = block_sum256(s);
        if (threadIdx.x == 0) g_part1[b] = t;
    }

    // ---- last-block final reduction of mean (deterministic fixed-order) ----
    __shared__ unsigned done;
    __threadfence();
    __syncthreads();
    if (threadIdx.x == 0) done = atomicAdd(&g_ctr1, 1u);
    __syncthreads();
    if (done == (unsigned)(MROWS + WSUM_BLOCKS - 1)) {
        float s = 0.f;
        for (int i = threadIdx.x; i < WSUM_BLOCKS; i += 256) s += g_part1[i];
        float t = block_sum256(s);
        if (threadIdx.x == 0) {
            g_wmean = t / (float)WN;
            g_ctr1 = 0;         // reset for next graph replay
            __threadfence();
        }
    }
}

// ---------------- k2: binarize W + |.| partials + beta (fused) ----------------
__global__ void k_binabs_beta(const float* __restrict__ w) {
    const float m = g_wmean;
    float s = 0.f;
    const float4* w4 = (const float4*)w;
    __half2* o = (__half2*)g_wb;
    // 16 floats per thread per iter via 4 independent float4 loads (MLP=4)
    for (int j = blockIdx.x * 256 + threadIdx.x; j < WN / 16; j += BIN_BLOCKS * 256) {
        float4 v[4];
#pragma unroll
        for (int q = 0; q < 4; q++) v[q] = w4[4 * j + q];
#pragma unroll
        for (int q = 0; q < 4; q++) {
            float a = v[q].x - m, b = v[q].y - m, c = v[q].z - m, d = v[q].w - m;
            s += fabsf(a) + fabsf(b) + fabsf(c) + fabsf(d);
            float sa = (a > 0.f) ? 1.f : ((a < 0.f) ? -1.f : 0.f);
            float sb = (b > 0.f) ? 1.f : ((b < 0.f) ? -1.f : 0.f);
            float sc = (c > 0.f) ? 1.f : ((c < 0.f) ? -1.f : 0.f);
            float sd = (d > 0.f) ? 1.f : ((d < 0.f) ? -1.f : 0.f);
            stcs2h(o + 8 * j + 2 * q, __floats2half2_rn(sa, sb), __floats2half2_rn(sc, sd));
        }
    }
    float t = block_sum256(s);
    if (threadIdx.x == 0) g_part2[blockIdx.x] = t;

    __shared__ unsigned done;
    __threadfence();
    __syncthreads();
    if (threadIdx.x == 0) done = atomicAdd(&g_ctr2, 1u);
    __syncthreads();
    if (done == (unsigned)(BIN_BLOCKS - 1)) {
        float s2 = 0.f;
        for (int i = threadIdx.x; i < BIN_BLOCKS; i += 256) s2 += g_part2[i];
        float t2 = block_sum256(s2);
        if (threadIdx.x == 0) {
            g_beta = t2 / (float)WN;
            g_ctr2 = 0;
            __threadfence();
        }
    }
}

// ---------------- PTX helpers (baseline sm_80-class only) ----------------
__device__ __forceinline__ uint32_t smem_u32(const void* p) {
    uint32_t a;
    asm("{ .reg .u64 t; cvta.to.shared.u64 t, %1; cvt.u32.u64 %0, t; }" : "=r"(a) : "l"(p));
    return a;
}
__device__ __forceinline__ void cpa16(uint32_t d, const void* g) {
    asm volatile("cp.async.cg.shared.global [%0], [%1], 16;" :: "r"(d), "l"(g) : "memory");
}
#define CP_COMMIT() asm volatile("cp.async.commit_group;" ::: "memory")
#define CP_WAIT1()  asm volatile("cp.async.wait_group 1;" ::: "memory")

__device__ __forceinline__ void ldsm4(uint32_t* r, uint32_t a) {
    asm volatile("ldmatrix.sync.aligned.m8n8.x4.shared.b16 {%0,%1,%2,%3}, [%4];"
                 : "=r"(r[0]), "=r"(r[1]), "=r"(r[2]), "=r"(r[3]) : "r"(a));
}
__device__ __forceinline__ void mma16816(float* c, const uint32_t* a, const uint32_t* b) {
    asm volatile("mma.sync.aligned.m16n8k16.row.col.f32.f16.f16.f32 "
                 "{%0,%1,%2,%3}, {%4,%5,%6,%7}, {%8,%9}, {%0,%1,%2,%3};"
                 : "+f"(c[0]), "+f"(c[1]), "+f"(c[2]), "+f"(c[3])
                 : "r"(a[0]), "r"(a[1]), "r"(a[2]), "r"(a[3]), "r"(b[0]), "r"(b[1]));
}

// ---------------- GEMM ----------------
__device__ __forceinline__ void load_stage(uint32_t sb, int s,
                                           const __half* Abase, const __half* Bbase,
                                           int chunk, int tid) {
    const uint32_t stA = sb + (uint32_t)s * STAGE_BYTES;
    const uint32_t stB = stA + A_BYTES;
    const size_t kb = (size_t)chunk * BK;
#pragma unroll
    for (int it = 0; it < 12; it++) {
        int i = tid + it * NTHR;
        if (i < BM * 8) {                 // A: 128 rows x 8 segments(16B)
            int r = i >> 3, cs = i & 7;
            const void* g = Abase + (size_t)r * DI + kb + cs * 8;
            uint32_t off = (uint32_t)(r * 128 + cs * 16);
            cpa16(stA + (off ^ ((uint32_t)(r & 7) << 4)), g);
        } else {                          // B: 256 rows x 8 segments
            int j = i - BM * 8;
            int r = j >> 3, cs = j & 7;
            const void* g = Bbase + (size_t)r * DI + kb + cs * 8;
            uint32_t off = (uint32_t)(r * 128 + cs * 16);
            cpa16(stB + (off ^ ((uint32_t)(r & 7) << 4)), g);
        }
    }
    CP_COMMIT();
}

__global__ void __launch_bounds__(NTHR, 1) k_gemm(float* __restrict__ out) {
    extern __shared__ char smem[];
    const uint32_t sb = smem_u32(smem);
    const int tid = threadIdx.x;
    const int wid = tid >> 5, lane = tid & 31;
    const int wm = wid >> 2, wn = wid & 3;           // warp grid 2(M) x 4(N), warp tile 64x64
    const int lr = lane & 7, sel = lane >> 3;
    const int g = lane >> 2, tc = lane & 3;

    // CTA swizzle: groups of 8 m-tiles x 16 n-tiles (128 CTAs ~ 1 wave) for L2 reuse
    const int grp = blockIdx.x >> 7;
    const int rem = blockIdx.x & 127;
    const int mt = grp * 8 + (rem & 7);              // 0..63
    const int nt = rem >> 3;                         // 0..15

    const __half* Abase = g_xn + (size_t)mt * BM * DI;
    const __half* Bbase = g_wb + (size_t)nt * BN * DI;

    float acc[4][8][4];
#pragma unroll
    for (int i = 0; i < 4; i++)
#pragma unroll
        for (int j = 0; j < 8; j++)
#pragma unroll
            for (int k = 0; k < 4; k++) acc[i][j][k] = 0.f;

    // A frag (m16k16 per ldsm4): rows wm*64 + lr + (sel&1)*8 + i*16, k-half (sel>>1)*16B
    const int a_row = wm * 64 + lr + (sel & 1) * 8;
    const uint32_t a_k2 = (uint32_t)((sel >> 1) * 16);      // bytes
    // B frag (k16n16 per ldsm4, [n][k] smem): n rows wn*64 + lr + (sel>>1)*8 + p*16, k-half (sel&1)*16B
    const int b_row = wn * 64 + lr + (sel >> 1) * 8;
    const uint32_t b_k2 = (uint32_t)((sel & 1) * 16);       // bytes
    const uint32_t xr = (uint32_t)lr << 4;

    // Double-buffered register fragments
    uint32_t af[2][4][4];
    uint32_t bf[2][4][4];

    // prologue: fill 3 of 4 stages
    load_stage(sb, 0, Abase, Bbase, 0, tid);
    load_stage(sb, 1, Abase, Bbase, 1, tid);
    load_stage(sb, 2, Abase, Bbase, 2, tid);
    CP_WAIT1();                     // chunks 0,1 complete
    __syncthreads();

    // preload kstep0 fragments of chunk 0 into buffer 0
    {
        const uint32_t sA = sb;
        const uint32_t sB = sA + A_BYTES;
#pragma unroll
        for (int i = 0; i < 4; i++)
            ldsm4(af[0][i], sA + (uint32_t)(a_row + i * 16) * 128 + (a_k2 ^ xr));
#pragma unroll
        for (int p = 0; p < 4; p++)
            ldsm4(bf[0][p], sB + (uint32_t)(b_row + p * 16) * 128 + (b_k2 ^ xr));
    }

    int s = 0;
    for (int ks = 0; ks < NCHUNK; ks++) {
        CP_WAIT1();                 // chunks 0..ks+1 complete
        __syncthreads();            // stage reuse + cross-warp visibility of chunks ks, ks+1

        {   // issue next-stage loads (always commit a group to keep wait bookkeeping exact)
            const int nxt = ks + 3;
            if (nxt < NCHUNK) {
                int sn = s + 3; if (sn >= NSTG) sn -= NSTG;
                load_stage(sb, sn, Abase, Bbase, nxt, tid);
            } else {
                CP_COMMIT();
            }
        }

        const uint32_t sA = sb + (uint32_t)s * STAGE_BYTES;
        const uint32_t sB = sA + A_BYTES;
        // next chunk's stage (for cross-chunk kstep0 prefetch; clamp at last chunk)
        int s2 = (ks + 1 < NCHUNK) ? (s + 1 == NSTG ? 0 : s + 1) : s;
        const uint32_t sA2 = sb + (uint32_t)s2 * STAGE_BYTES;
        const uint32_t sB2 = sA2 + A_BYTES;

#pragma unroll
        for (int kk = 0; kk < 4; kk++) {             // 4 ksteps of 16 within BK=64
            const int cb = kk & 1, nb = cb ^ 1;
            // prefetch fragments for next kstep (or next chunk's kstep0) into other buffer
            const uint32_t nA = (kk < 3) ? sA : sA2;
            const uint32_t nB = (kk < 3) ? sB : sB2;
            const uint32_t ncol = (kk < 3) ? (uint32_t)((kk + 1) * 32) : 0u;
#pragma unroll
            for (int i = 0; i < 4; i++)
                ldsm4(af[nb][i], nA + (uint32_t)(a_row + i * 16) * 128 + ((ncol + a_k2) ^ xr));
#pragma unroll
            for (int p = 0; p < 4; p++)
                ldsm4(bf[nb][p], nB + (uint32_t)(b_row + p * 16) * 128 + ((ncol + b_k2) ^ xr));
            // compute current kstep
#pragma unroll
            for (int i = 0; i < 4; i++)
#pragma unroll
                for (int j = 0; j < 8; j++)
                    mma16816(acc[i][j], af[cb][i], &bf[cb][j >> 1][(j & 1) * 2]);
        }

        s++; if (s == NSTG) s = 0;
    }

    // epilogue (streaming stores: out is write-once)
    const float beta = g_beta;
    const int rbase = mt * BM + wm * 64 + g;
    const int cbase = nt * BN + wn * 64 + tc * 2;
#pragma unroll
    for (int i = 0; i < 4; i++) {
#pragma unroll
        for (int j = 0; j < 8; j += 2) {
            const int row = rbase + i * 16;
            const int col = cbase + j * 8;
            float2 v0 = make_float2(acc[i][j][0] * beta, acc[i][j][1] * beta);
            float2 v1 = make_float2(acc[i][j][2] * beta, acc[i][j][3] * beta);
            float2 w0 = make_float2(acc[i][j + 1][0] * beta, acc[i][j + 1][1] * beta);
            float2 w1 = make_float2(acc[i][j + 1][2] * beta, acc[i][j + 1][3] * beta);
            asm volatile("st.global.cs.v2.f32 [%0], {%1,%2};" :: "l"(out + (size_t)row * NOUT + col), "f"(v0.x), "f"(v0.y) : "memory");
            asm volatile("st.global.cs.v2.f32 [%0], {%1,%2};" :: "l"(out + (size_t)(row + 8) * NOUT + col), "f"(v1.x), "f"(v1.y) : "memory");
            asm volatile("st.global.cs.v2.f32 [%0], {%1,%2};" :: "l"(out + (size_t)row * NOUT + col + 8), "f"(w0.x), "f"(w0.y) : "memory");
            asm volatile("st.global.cs.v2.f32 [%0], {%1,%2};" :: "l"(out + (size_t)(row + 8) * NOUT + col + 8), "f"(w1.x), "f"(w1.y) : "memory");
        }
    }
}

// ---------------- launch ----------------
extern "C" void kernel_launch(void* const* d_in, const int* in_sizes, int n_in,
                              void* d_out, int out_size) {
    (void)in_sizes; (void)n_in; (void)out_size;
    const float* x = (const float*)d_in[0];
    const float* w = (const float*)d_in[1];
    float* out = (float*)d_out;

    cudaFuncSetAttribute(k_gemm, cudaFuncAttributeMaxDynamicSharedMemorySize, SMEM_TOTAL);

    k_ln_wsum<<<MROWS + WSUM_BLOCKS, 256>>>(x, w);
    k_binabs_beta<<<BIN_BLOCKS, 256>>>(w);
    k_gemm<<<(MROWS / BM) * (NOUT / BN), NTHR, SMEM_TOTAL>>>(out);
}